// round 14
// baseline (speedup 1.0000x reference)
#include <cuda_runtime.h>
#include <cuda_bf16.h>
#include <math.h>
#include <stdint.h>

#define BATCH 512
#define HID   512
#define WDIM  1024
#define VOCAB 4004
#define VPAD  4096
#define TSTEPS 27
#define SLEN  80
#define NGATE 2048
#define LSTM_IN 1536

typedef unsigned long long ull;

// ---------------- device scratch ----------------
__device__ float g_a2[HID];
__device__ float g_a1[HID];
__device__ float g_a0e[HID];
__device__ float g_ctx[BATCH * HID];
__device__ float g_c[BATCH * HID];
__device__ float g_Gbase[BATCH * NGATE];      // permuted cols
__device__ float g_Eproj[VOCAB * NGATE];      // permuted cols
__device__ ull   g_tokpack[2][BATCH];
__device__ __align__(16) __nv_bfloat16 g_h2[2][2][BATCH * HID];
__device__ __align__(16) __nv_bfloat16 g_Whh2[2][NGATE * HID];    // rows gate-permuted
__device__ __align__(16) __nv_bfloat16 g_Wout2[2][VPAD * HID];    // rows >= VOCAB zero
__device__ __align__(16) __nv_bfloat16 g_emb2[2][VPAD * WDIM];    // rows >= VOCAB zero
__device__ __align__(16) __nv_bfloat16 g_Wihw2[2][NGATE * WDIM];  // rows gate-permuted

// ---------------- helpers ----------------
__device__ __forceinline__ ull ffma2(ull a, ull b, ull c) {
    ull d;
    asm("fma.rn.f32x2 %0, %1, %2, %3;" : "=l"(d) : "l"(a), "l"(b), "l"(c));
    return d;
}
__device__ __forceinline__ float2 unpack2(ull v) {
    float2 r;
    asm("mov.b64 {%0, %1}, %2;" : "=f"(r.x), "=f"(r.y) : "l"(v));
    return r;
}
__device__ __forceinline__ unsigned f2ord(float x) {
    unsigned u = __float_as_uint(x);
    return (u & 0x80000000u) ? ~u : (u | 0x80000000u);
}
__device__ __forceinline__ int decode_tok(ull p) {
    return (int)(0xFFFFFFFFu - (unsigned)(p & 0xFFFFFFFFull));
}
__device__ __forceinline__ float sigmoidf_(float x) { return 1.0f / (1.0f + expf(-x)); }
__device__ __forceinline__ int permrow(int n) { return ((n & 3) << 9) | (n >> 2); }
__device__ __forceinline__ void split2(float x, __nv_bfloat16& a, __nv_bfloat16& b) {
    a = __float2bfloat16(x);
    b = __float2bfloat16(x - __bfloat162float(a));
}

#define CP_ASYNC16(dst, src) \
    asm volatile("cp.async.cg.shared.global [%0], [%1], 16;\n" :: "r"(dst), "l"(src))
#define CP_COMMIT() asm volatile("cp.async.commit_group;\n")
#define CP_WAIT1()  asm volatile("cp.async.wait_group 1;\n")
#define CP_WAIT0()  asm volatile("cp.async.wait_group 0;\n")

__device__ __forceinline__ void ldm_x4(uint32_t* r, uint32_t addr) {
    asm volatile("ldmatrix.sync.aligned.m8n8.x4.shared.b16 {%0,%1,%2,%3}, [%4];"
        : "=r"(r[0]), "=r"(r[1]), "=r"(r[2]), "=r"(r[3]) : "r"(addr));
}
__device__ __forceinline__ void mma16816(float* d, const uint32_t* a,
                                         uint32_t b0, uint32_t b1) {
    asm volatile("mma.sync.aligned.m16n8k16.row.col.f32.bf16.bf16.f32 "
        "{%0,%1,%2,%3}, {%4,%5,%6,%7}, {%8,%9}, {%0,%1,%2,%3};"
        : "+f"(d[0]), "+f"(d[1]), "+f"(d[2]), "+f"(d[3])
        : "r"(a[0]), "r"(a[1]), "r"(a[2]), "r"(a[3]), "r"(b0), "r"(b1));
}

// smem totals (host side): BN=64 -> 62464 ; BN=128 -> 82944
#define MM_SMEM_64   62464
#define MM_SMEM_128  82944

// ---------------- init ----------------
__global__ void init_hc_kernel(const float* __restrict__ h0) {
    int b = blockIdx.x, u = threadIdx.x;
    __nv_bfloat16 s0, s1;
    split2(h0[b * HID + u], s0, s1);
    g_h2[0][0][b * HID + u] = s0;
    g_h2[0][1][b * HID + u] = s1;
    g_c[b * HID + u] = 0.0f;
    if (u == 0) { g_tokpack[0][b] = 0ull; g_tokpack[1][b] = 0ull; }
}

// which: 0=Whh(perm,HID), 1=Wout(pad,HID), 2=emb(pad,WDIM), 3=Wih_word(perm,WDIM)
__global__ void split_kernel(const float* __restrict__ src, int which) {
    int r = blockIdx.x;
    int cols = (which >= 2) ? WDIM : HID;
    int srcld = (which == 3) ? LSTM_IN : cols;
    for (int k = threadIdx.x; k < cols; k += 256) {
        float x;
        if (which == 0)      x = src[(size_t)permrow(r) * srcld + k];
        else if (which == 1) x = (r < VOCAB) ? src[(size_t)r * srcld + k] : 0.0f;
        else if (which == 2) x = (r < VOCAB) ? src[(size_t)r * srcld + k] : 0.0f;
        else                 x = src[(size_t)permrow(r) * srcld + k];
        __nv_bfloat16 s0, s1;
        split2(x, s0, s1);
        size_t o = (size_t)r * cols + k;
        if (which == 0)      { g_Whh2[0][o] = s0;  g_Whh2[1][o] = s1; }
        else if (which == 1) { g_Wout2[0][o] = s0; g_Wout2[1][o] = s1; }
        else if (which == 2) { g_emb2[0][o] = s0;  g_emb2[1][o] = s1; }
        else                 { g_Wihw2[0][o] = s0; g_Wihw2[1][o] = s1; }
    }
}

// ---------------- a-chain mat-vecs ----------------
__global__ void matvecT_kernel(const float* __restrict__ Mt, int ld,
                               const float* __restrict__ vin_ext, int stage) {
    __shared__ float red[256];
    int j = blockIdx.x;
    const float* vin = (stage == 0) ? vin_ext : (stage == 1 ? g_a2 : g_a1);
    float acc = 0.0f;
    for (int h = threadIdx.x; h < HID; h += 256)
        acc += Mt[(size_t)h * ld + j] * vin[h];
    red[threadIdx.x] = acc;
    __syncthreads();
    for (int s = 128; s > 0; s >>= 1) {
        if (threadIdx.x < s) red[threadIdx.x] += red[threadIdx.x + s];
        __syncthreads();
    }
    if (threadIdx.x == 0) {
        float r = red[0];
        if (stage == 0)      g_a2[j]  = r;
        else if (stage == 1) g_a1[j]  = r;
        else                 g_a0e[j] = r;
    }
}

// ---------------- attention context (step-invariant) ----------------
__global__ void attn_ctx_kernel(const float* __restrict__ enc) {
    __shared__ float sa[HID];
    __shared__ float sE[SLEN];
    __shared__ float sW[SLEN];
    int b = blockIdx.x, tid = threadIdx.x;
    sa[tid] = g_a0e[tid];
    sa[tid + 256] = g_a0e[tid + 256];
    __syncthreads();
    int w = tid >> 5, lane = tid & 31;
    for (int s = w; s < SLEN; s += 8) {
        const float* row = enc + ((size_t)b * SLEN + s) * HID;
        float acc = 0.0f;
        for (int k = lane; k < HID; k += 32) acc += row[k] * sa[k];
        #pragma unroll
        for (int off = 16; off > 0; off >>= 1)
            acc += __shfl_xor_sync(0xffffffffu, acc, off);
        if (lane == 0) sE[s] = acc;
    }
    __syncthreads();
    if (tid < 32) {
        float v0 = (tid < SLEN) ? sE[tid] : -INFINITY;
        float v1 = (tid + 32 < SLEN) ? sE[tid + 32] : -INFINITY;
        float v2 = (tid + 64 < SLEN) ? sE[tid + 64] : -INFINITY;
        float m = fmaxf(v0, fmaxf(v1, v2));
        #pragma unroll
        for (int off = 16; off > 0; off >>= 1)
            m = fmaxf(m, __shfl_xor_sync(0xffffffffu, m, off));
        float e0 = (tid < SLEN) ? expf(v0 - m) : 0.0f;
        float e1 = (tid + 32 < SLEN) ? expf(v1 - m) : 0.0f;
        float e2 = (tid + 64 < SLEN) ? expf(v2 - m) : 0.0f;
        float s = e0 + e1 + e2;
        #pragma unroll
        for (int off = 16; off > 0; off >>= 1)
            s += __shfl_xor_sync(0xffffffffu, s, off);
        if (tid < SLEN)      sW[tid]      = e0 / s;
        if (tid + 32 < SLEN) sW[tid + 32] = e1 / s;
        if (tid + 64 < SLEN) sW[tid + 64] = e2 / s;
    }
    __syncthreads();
    for (int h = tid; h < HID; h += 256) {
        float acc = 0.0f;
        for (int s = 0; s < SLEN; s++)
            acc += sW[s] * enc[((size_t)b * SLEN + s) * HID + h];
        g_ctx[b * HID + h] = acc;
    }
}

// ---------------- FFMA2 Gbase GEMM (R4-proven; small, one-shot) -------------
__global__ __launch_bounds__(128, 4)
void pre_gemm_gbase(const float* __restrict__ Bp,
                    const float* __restrict__ bias1, const float* __restrict__ bias2) {
    __shared__ __align__(16) float As[2][64 * 32];
    __shared__ __align__(16) float Bs[2][64 * 32];

    const int tid = threadIdx.x;
    const int bm = blockIdx.y * 64;
    const int bn = blockIdx.x * 64;
    const int tm = tid >> 3;
    const int tn = tid & 7;

    const uint32_t sA = (uint32_t)__cvta_generic_to_shared(&As[0][0]);
    const uint32_t sB = (uint32_t)__cvta_generic_to_shared(&Bs[0][0]);

    const int ldrow = tid >> 1;
    const int ldcb  = (tid & 1) * 4;
    const int aswz  = (ldrow >> 2) & 7;
    const int bswz  = (ldrow >> 3) & 7;

    const float* a_srcbase = g_ctx + (size_t)(bm + ldrow) * HID + ldcb * 4;
    const float* b_srcbase = Bp + (size_t)permrow(bn + ldrow) * LSTM_IN + ldcb * 4;

    const uint32_t a_dst = sA + ldrow * 128;
    const uint32_t b_dst = sB + ldrow * 128;

    ull acc[4][8];
    #pragma unroll
    for (int i = 0; i < 4; i++)
        #pragma unroll
        for (int j = 0; j < 8; j++) acc[i][j] = 0ull;

    const int nch = HID >> 5;
    {
        #pragma unroll
        for (int jj = 0; jj < 4; jj++) {
            int c = ldcb + jj;
            CP_ASYNC16(a_dst + ((c ^ aswz) << 4), a_srcbase + jj * 4);
            CP_ASYNC16(b_dst + ((c ^ bswz) << 4), b_srcbase + jj * 4);
        }
        CP_COMMIT();
    }
    for (int ch = 0; ch < nch; ch++) {
        if (ch + 1 < nch) {
            int k0 = (ch + 1) << 5;
            uint32_t soff = ((ch + 1) & 1) ? 8192u : 0u;
            #pragma unroll
            for (int jj = 0; jj < 4; jj++) {
                int c = ldcb + jj;
                CP_ASYNC16(a_dst + soff + ((c ^ aswz) << 4), a_srcbase + k0 + jj * 4);
                CP_ASYNC16(b_dst + soff + ((c ^ bswz) << 4), b_srcbase + k0 + jj * 4);
            }
            CP_COMMIT();
            CP_WAIT1();
        } else {
            CP_WAIT0();
        }
        __syncthreads();

        const float* as = As[ch & 1];
        const float* bs = Bs[ch & 1];
        #pragma unroll
        for (int c = 0; c < 8; c++) {
            const int aoff = (c ^ (tm & 7)) << 2;
            const int boff = (c ^ tn) << 2;
            ulonglong2 av0 = *(const ulonglong2*)&as[(tm * 4 + 0) * 32 + aoff];
            ulonglong2 av1 = *(const ulonglong2*)&as[(tm * 4 + 1) * 32 + aoff];
            ulonglong2 av2 = *(const ulonglong2*)&as[(tm * 4 + 2) * 32 + aoff];
            ulonglong2 av3 = *(const ulonglong2*)&as[(tm * 4 + 3) * 32 + aoff];
            #pragma unroll
            for (int j = 0; j < 8; j++) {
                ulonglong2 bv = *(const ulonglong2*)&bs[(tn * 8 + j) * 32 + boff];
                acc[0][j] = ffma2(av0.x, bv.x, acc[0][j]);
                acc[0][j] = ffma2(av0.y, bv.y, acc[0][j]);
                acc[1][j] = ffma2(av1.x, bv.x, acc[1][j]);
                acc[1][j] = ffma2(av1.y, bv.y, acc[1][j]);
                acc[2][j] = ffma2(av2.x, bv.x, acc[2][j]);
                acc[2][j] = ffma2(av2.y, bv.y, acc[2][j]);
                acc[3][j] = ffma2(av3.x, bv.x, acc[3][j]);
                acc[3][j] = ffma2(av3.y, bv.y, acc[3][j]);
            }
        }
        __syncthreads();
    }

    const int ncol = bn + tn * 8;
    float badd[8];
    #pragma unroll
    for (int j = 0; j < 8; j++) {
        int pr = permrow(ncol + j);
        badd[j] = bias1[pr] + bias2[pr];
    }
    #pragma unroll
    for (int i = 0; i < 4; i++) {
        int m = bm + tm * 4 + i;
        float2 p0, p1, p2, p3;
        p0 = unpack2(acc[i][0]); p1 = unpack2(acc[i][1]);
        p2 = unpack2(acc[i][2]); p3 = unpack2(acc[i][3]);
        float4 v0 = make_float4(p0.x + p0.y + badd[0], p1.x + p1.y + badd[1],
                                p2.x + p2.y + badd[2], p3.x + p3.y + badd[3]);
        p0 = unpack2(acc[i][4]); p1 = unpack2(acc[i][5]);
        p2 = unpack2(acc[i][6]); p3 = unpack2(acc[i][7]);
        float4 v1 = make_float4(p0.x + p0.y + badd[4], p1.x + p1.y + badd[5],
                                p2.x + p2.y + badd[6], p3.x + p3.y + badd[7]);
        *reinterpret_cast<float4*>(g_Gbase + (size_t)m * NGATE + ncol)     = v0;
        *reinterpret_cast<float4*>(g_Gbase + (size_t)m * NGATE + ncol + 4) = v1;
    }
}

// ---------------- mma.sync 2-split / 3-product GEMM, 128xBN tile ------------
// BN = 64 (MODE 1) or 128 (MODE 2/3) — wider N-tiles cut redundant A loads.
// products via PA/PB arrays: (0,0), (0,1), (1,0); (1,1) omitted (~2^-32 rel).
// MODE 1: gates = h[t] @ Whh^T + Gbase + Eproj[tok]; fused LSTM -> h[t+1], c
// MODE 2: logits = h[t+1] @ Wout^T + out_b; seq store + argmax
// MODE 3: Eproj = emb @ Wih_word^T (one-shot precompute)
template <int MODE>
__global__ __launch_bounds__(256)
void mma_gemm(int t, const float* __restrict__ bias1,
              float* __restrict__ seq, float* __restrict__ pred) {
    constexpr int BN   = (MODE == 1) ? 64 : 128;
    constexpr int WN   = BN / 2;          // warp N tile
    constexpr int NT   = BN / 16;         // 8-col fragments per warp
    constexpr int NG   = BN / 32;         // 16-row B ldmatrix groups per warp
    constexpr uint32_t ASZ = 10240u;
    constexpr uint32_t BSZ = (uint32_t)BN * 80u;
    constexpr uint32_t STG = 2u * ASZ + 2u * BSZ;
    constexpr uint32_t SBB = 2u * STG;
    constexpr uint32_t SBT = SBB + 512u;
    constexpr int ACH = 1024;             // A 16B chunks per BK=32 chunk
    constexpr int BCH = BN * 8;           // B 16B chunks per BK=32 chunk
    constexpr int PER = (ACH + BCH) / 256;
    constexpr int EPS = BN + 4;           // epilogue smem row stride (floats)

    extern __shared__ __align__(16) char smem[];
    const uint32_t sbase = (uint32_t)__cvta_generic_to_shared(smem);

    const int tid = threadIdx.x;
    const int wid = tid >> 5;
    const int lane = tid & 31;
    const int bm = blockIdx.y * 128;
    const int bn = blockIdx.x * BN;
    const int wm = (wid & 3) * 32;
    const int wn = (wid >> 2) * WN;

    const int K = (MODE == 3) ? WDIM : HID;
    const __nv_bfloat16* Aps[2];
    const __nv_bfloat16* Bps[2];
    if (MODE == 1) {
        Aps[0] = g_h2[t & 1][0];  Aps[1] = g_h2[t & 1][1];
        Bps[0] = g_Whh2[0];       Bps[1] = g_Whh2[1];
    } else if (MODE == 2) {
        Aps[0] = g_h2[(t + 1) & 1][0]; Aps[1] = g_h2[(t + 1) & 1][1];
        Bps[0] = g_Wout2[0];           Bps[1] = g_Wout2[1];
    } else {
        Aps[0] = g_emb2[0];  Aps[1] = g_emb2[1];
        Bps[0] = g_Wihw2[0]; Bps[1] = g_Wihw2[1];
    }

    int* stok = (int*)(smem + SBT);
    float* sbias = (float*)(smem + SBB);
    if (MODE == 1 && tid < 128)
        stok[tid] = (t == 0) ? 1 : decode_tok(g_tokpack[(t - 1) & 1][bm + tid]);
    if (MODE == 2) {
        if (blockIdx.x == 0 && tid < 128) g_tokpack[(t + 1) & 1][bm + tid] = 0ull;
        if (tid < BN) {
            int n = bn + tid;
            sbias[tid] = (n < VOCAB) ? bias1[n] : -3e38f;
        }
    }

    float acc[2][NT][4];
    #pragma unroll
    for (int i = 0; i < 2; i++)
        #pragma unroll
        for (int j = 0; j < NT; j++)
            #pragma unroll
            for (int k = 0; k < 4; k++) acc[i][j][k] = 0.0f;

    auto load_chunk = [&](int ch, int st) {
        const int k0 = ch << 5;
        #pragma unroll
        for (int i = 0; i < PER; i++) {
            int idx = i * 256 + tid;
            uint32_t dst;
            const __nv_bfloat16* src;
            if (idx < ACH) {
                int s = idx >> 9, rem = idx & 511, r = rem >> 2, c = rem & 3;
                dst = sbase + st * STG + s * ASZ + r * 80 + c * 16;
                src = Aps[s] + (size_t)(bm + r) * K + k0 + c * 8;
            } else {
                int j = idx - ACH;
                int s = j / (BN * 4), rem = j % (BN * 4), r = rem >> 2, c = rem & 3;
                dst = sbase + st * STG + 2 * ASZ + s * BSZ + r * 80 + c * 16;
                src = Bps[s] + (size_t)(bn + r) * K + k0 + c * 8;
            }
            CP_ASYNC16(dst, src);
        }
        CP_COMMIT();
    };

    const int nch = K >> 5;
    load_chunk(0, 0);
    for (int ch = 0; ch < nch; ch++) {
        if (ch + 1 < nch) { load_chunk(ch + 1, (ch + 1) & 1); CP_WAIT1(); }
        else              { CP_WAIT0(); }
        __syncthreads();

        const int st = ch & 1;
        #pragma unroll
        for (int ks = 0; ks < 2; ks++) {
            uint32_t af[2][2][4], bf[2][NG][4];
            #pragma unroll
            for (int s = 0; s < 2; s++) {
                #pragma unroll
                for (int mt = 0; mt < 2; mt++)
                    ldm_x4(af[s][mt], sbase + st * STG + s * ASZ +
                           (wm + mt * 16 + (lane & 15)) * 80 + ks * 32 +
                           ((lane >> 4) << 4));
                #pragma unroll
                for (int g = 0; g < NG; g++)
                    ldm_x4(bf[s][g], sbase + st * STG + 2 * ASZ + s * BSZ +
                           (wn + g * 16 + (lane & 15)) * 80 + ks * 32 +
                           ((lane >> 4) << 4));
            }
            const int PA[3] = {0, 0, 1};
            const int PB[3] = {0, 1, 0};
            #pragma unroll
            for (int p = 0; p < 3; p++) {
                #pragma unroll
                for (int mt = 0; mt < 2; mt++)
                    #pragma unroll
                    for (int nt = 0; nt < NT; nt++) {
                        int g = nt >> 1, h = nt & 1;
                        mma16816(acc[mt][nt], af[PA[p]][mt],
                                 bf[PB[p]][g][h], bf[PB[p]][g][h + 2]);
                    }
            }
        }
        __syncthreads();
    }

    // accumulators -> smem tile [128][EPS] f32 (reuses stage buffers)
    float* ep = (float*)smem;
    #pragma unroll
    for (int mt = 0; mt < 2; mt++)
        #pragma unroll
        for (int nt = 0; nt < NT; nt++) {
            int row = wm + mt * 16 + (lane >> 2);
            int col = wn + nt * 8 + (lane & 3) * 2;
            float b0 = 0.0f, b1 = 0.0f;
            if (MODE == 2) { b0 = sbias[col]; b1 = sbias[col + 1]; }
            ep[row * EPS + col]           = acc[mt][nt][0] + b0;
            ep[row * EPS + col + 1]       = acc[mt][nt][1] + b1;
            ep[(row + 8) * EPS + col]     = acc[mt][nt][2] + b0;
            ep[(row + 8) * EPS + col + 1] = acc[mt][nt][3] + b1;
        }
    __syncthreads();

    const int m = tid >> 1;
    const int mg = bm + m;
    if (MODE == 1) {
        const int tok = stok[m];
        const int uo = (tid & 1) * 8;
        const int ho = (t + 1) & 1;
        #pragma unroll
        for (int j = 0; j < 8; j++) {
            int col = (uo + j) * 4;
            int gcol = bn + col;
            int u = gcol >> 2;
            float4 gb = *(const float4*)&g_Gbase[(size_t)mg * NGATE + gcol];
            float4 epj = *(const float4*)&g_Eproj[(size_t)tok * NGATE + gcol];
            float gi = ep[m * EPS + col]     + gb.x + epj.x;
            float gf = ep[m * EPS + col + 1] + gb.y + epj.y;
            float gg = ep[m * EPS + col + 2] + gb.z + epj.z;
            float go = ep[m * EPS + col + 3] + gb.w + epj.w;
            float cn = sigmoidf_(gf) * g_c[mg * HID + u] + sigmoidf_(gi) * tanhf(gg);
            g_c[mg * HID + u] = cn;
            float hn = sigmoidf_(go) * tanhf(cn);
            __nv_bfloat16 s0, s1;
            split2(hn, s0, s1);
            g_h2[ho][0][mg * HID + u] = s0;
            g_h2[ho][1][mg * HID + u] = s1;
        }
        if (blockIdx.x == 0 && (tid & 1) == 0 && t > 0 && pred)
            pred[mg * TSTEPS + (t - 1)] = (float)tok;
    } else if (MODE == 2) {
        const int cs = (tid & 1) * WN;
        ull best = 0ull;
        #pragma unroll
        for (int k = 0; k < WN; k++) {
            float v = ep[m * EPS + cs + k];
            unsigned n = (unsigned)(bn + cs + k);
            ull cand = ((ull)f2ord(v) << 32) | (ull)(0xFFFFFFFFu - n);
            if (cand > best) best = cand;
        }
        ull o = __shfl_xor_sync(0xffffffffu, best, 1);
        if (o > best) best = o;
        if ((tid & 1) == 0) atomicMax(&g_tokpack[t & 1][mg], best);
        if (seq) {
            float* orow = seq + (size_t)mg * (TSTEPS * VOCAB) + (size_t)t * VOCAB;
            #pragma unroll
            for (int k4 = 0; k4 < WN / 4; k4++) {
                int n = bn + cs + k4 * 4;
                if (n + 3 < VOCAB) {
                    *(float4*)&orow[n] = make_float4(
                        ep[m * EPS + cs + k4 * 4],     ep[m * EPS + cs + k4 * 4 + 1],
                        ep[m * EPS + cs + k4 * 4 + 2], ep[m * EPS + cs + k4 * 4 + 3]);
                } else {
                    for (int q = 0; q < 4; q++)
                        if (n + q < VOCAB) orow[n + q] = ep[m * EPS + cs + k4 * 4 + q];
                }
            }
        }
    } else {  // MODE 3: Eproj store
        if (mg < VOCAB) {
            const int cs = (tid & 1) * WN;
            float* orow = g_Eproj + (size_t)mg * NGATE + bn;
            #pragma unroll
            for (int k4 = 0; k4 < WN / 4; k4++)
                *(float4*)&orow[cs + k4 * 4] = make_float4(
                    ep[m * EPS + cs + k4 * 4],     ep[m * EPS + cs + k4 * 4 + 1],
                    ep[m * EPS + cs + k4 * 4 + 2], ep[m * EPS + cs + k4 * 4 + 3]);
        }
    }
}

// ---------------- final pred ----------------
__global__ void final_pred_kernel(float* __restrict__ pred) {
    int b = threadIdx.x;
    pred[b * TSTEPS + (TSTEPS - 1)] = (float)decode_tok(g_tokpack[(TSTEPS - 1) & 1][b]);
}

// ---------------- launch ----------------
extern "C" void kernel_launch(void* const* d_in, const int* in_sizes, int n_in,
                              void* d_out, int out_size) {
    const float* enc_last = (const float*)d_in[0];
    const float* enc_out  = (const float*)d_in[1];
    const float* emb      = (const float*)d_in[2];
    const float* w1       = (const float*)d_in[3];
    const float* w2       = (const float*)d_in[5];
    const float* w3       = (const float*)d_in[7];
    const float* wv       = (const float*)d_in[9];
    const float* w_ih     = (const float*)d_in[10];
    const float* w_hh     = (const float*)d_in[11];
    const float* b_ih     = (const float*)d_in[12];
    const float* b_hh     = (const float*)d_in[13];
    const float* out_w    = (const float*)d_in[14];
    const float* out_b    = (const float*)d_in[15];

    float* out = (float*)d_out;
    const long long SEQ = (long long)BATCH * TSTEPS * VOCAB;
    const long long PRED = (long long)BATCH * TSTEPS;
    float* seq_ptr = ((long long)out_size >= SEQ) ? out : nullptr;
    float* pred_ptr = ((long long)out_size >= SEQ + PRED) ? (out + SEQ) : nullptr;

    cudaFuncSetAttribute(mma_gemm<1>, cudaFuncAttributeMaxDynamicSharedMemorySize, MM_SMEM_64);
    cudaFuncSetAttribute(mma_gemm<2>, cudaFuncAttributeMaxDynamicSharedMemorySize, MM_SMEM_128);
    cudaFuncSetAttribute(mma_gemm<3>, cudaFuncAttributeMaxDynamicSharedMemorySize, MM_SMEM_128);

    // precompute
    init_hc_kernel<<<BATCH, HID>>>(enc_last);
    matvecT_kernel<<<HID, 256>>>(w3, HID, wv, 0);
    matvecT_kernel<<<HID, 256>>>(w2, HID, nullptr, 1);
    matvecT_kernel<<<HID, 256>>>(w1, WDIM, nullptr, 2);
    attn_ctx_kernel<<<BATCH, 256>>>(enc_out);

    split_kernel<<<NGATE, 256>>>(w_hh, 0);   // Whh2 (perm)
    split_kernel<<<VPAD, 256>>>(out_w, 1);   // Wout2 (pad)
    split_kernel<<<VPAD, 256>>>(emb, 2);     // emb2 (pad)
    split_kernel<<<NGATE, 256>>>(w_ih, 3);   // Wihw2 (perm, word cols)

    pre_gemm_gbase<<<dim3(NGATE / 64, BATCH / 64), 128>>>(w_ih + WDIM, b_ih, b_hh);

    // Eproj on tensor cores (one-shot, BN=128)
    mma_gemm<3><<<dim3(NGATE / 128, VPAD / 128), 256, MM_SMEM_128>>>(
        0, nullptr, nullptr, nullptr);

    // 27 decode steps on mma.sync tensor cores
    for (int t = 0; t < TSTEPS; t++) {
        mma_gemm<1><<<dim3(NGATE / 64, BATCH / 128), 256, MM_SMEM_64>>>(
            t, nullptr, nullptr, pred_ptr);
        mma_gemm<2><<<dim3(VPAD / 128, BATCH / 128), 256, MM_SMEM_128>>>(
            t, out_b, seq_ptr, nullptr);
    }
    if (pred_ptr)
        final_pred_kernel<<<1, BATCH>>>(pred_ptr);
}

// round 16
// speedup vs baseline: 1.0205x; 1.0205x over previous
#include <cuda_runtime.h>
#include <cuda_bf16.h>
#include <math.h>
#include <stdint.h>

#define BATCH 512
#define HID   512
#define WDIM  1024
#define VOCAB 4004
#define VPAD  4096
#define TSTEPS 27
#define SLEN  80
#define NGATE 2048
#define LSTM_IN 1536

typedef unsigned long long ull;

// ---------------- device scratch ----------------
__device__ float g_a2[HID];
__device__ float g_a1[HID];
__device__ float g_a0e[HID];
__device__ float g_ctx[BATCH * HID];
__device__ float g_c[BATCH * HID];
__device__ float g_Gbase[BATCH * NGATE];      // permuted cols
__device__ float g_Eproj[VOCAB * NGATE];      // permuted cols
__device__ ull   g_tokpack[2][BATCH];
__device__ __align__(16) __nv_bfloat16 g_h2[2][2][BATCH * HID];
__device__ __align__(16) __nv_bfloat16 g_Whh2[2][NGATE * HID];    // rows gate-permuted
__device__ __align__(16) __nv_bfloat16 g_Wout2[2][VPAD * HID];    // rows >= VOCAB zero
__device__ __align__(16) __nv_bfloat16 g_emb2[2][VPAD * WDIM];    // rows >= VOCAB zero
__device__ __align__(16) __nv_bfloat16 g_Wihw2[2][NGATE * WDIM];  // rows gate-permuted

// ---------------- helpers ----------------
__device__ __forceinline__ ull ffma2(ull a, ull b, ull c) {
    ull d;
    asm("fma.rn.f32x2 %0, %1, %2, %3;" : "=l"(d) : "l"(a), "l"(b), "l"(c));
    return d;
}
__device__ __forceinline__ float2 unpack2(ull v) {
    float2 r;
    asm("mov.b64 {%0, %1}, %2;" : "=f"(r.x), "=f"(r.y) : "l"(v));
    return r;
}
__device__ __forceinline__ unsigned f2ord(float x) {
    unsigned u = __float_as_uint(x);
    return (u & 0x80000000u) ? ~u : (u | 0x80000000u);
}
__device__ __forceinline__ int decode_tok(ull p) {
    return (int)(0xFFFFFFFFu - (unsigned)(p & 0xFFFFFFFFull));
}
__device__ __forceinline__ float sigmoidf_(float x) { return 1.0f / (1.0f + expf(-x)); }
__device__ __forceinline__ int permrow(int n) { return ((n & 3) << 9) | (n >> 2); }
__device__ __forceinline__ void split2(float x, __nv_bfloat16& a, __nv_bfloat16& b) {
    a = __float2bfloat16(x);
    b = __float2bfloat16(x - __bfloat162float(a));
}

#define CP_ASYNC16(dst, src) \
    asm volatile("cp.async.cg.shared.global [%0], [%1], 16;\n" :: "r"(dst), "l"(src))
#define CP_COMMIT() asm volatile("cp.async.commit_group;\n")
#define CP_WAIT1()  asm volatile("cp.async.wait_group 1;\n")
#define CP_WAIT0()  asm volatile("cp.async.wait_group 0;\n")

__device__ __forceinline__ void ldm_x4(uint32_t* r, uint32_t addr) {
    asm volatile("ldmatrix.sync.aligned.m8n8.x4.shared.b16 {%0,%1,%2,%3}, [%4];"
        : "=r"(r[0]), "=r"(r[1]), "=r"(r[2]), "=r"(r[3]) : "r"(addr));
}
__device__ __forceinline__ void mma16816(float* d, const uint32_t* a,
                                         uint32_t b0, uint32_t b1) {
    asm volatile("mma.sync.aligned.m16n8k16.row.col.f32.bf16.bf16.f32 "
        "{%0,%1,%2,%3}, {%4,%5,%6,%7}, {%8,%9}, {%0,%1,%2,%3};"
        : "+f"(d[0]), "+f"(d[1]), "+f"(d[2]), "+f"(d[3])
        : "r"(a[0]), "r"(a[1]), "r"(a[2]), "r"(a[3]), "r"(b0), "r"(b1));
}

// smem totals (host side): BN=64 -> 62464 ; BN=128 -> 82944
#define MM_SMEM_64   62464
#define MM_SMEM_128  82944

// ---------------- init ----------------
__global__ void init_hc_kernel(const float* __restrict__ h0) {
    int b = blockIdx.x, u = threadIdx.x;
    __nv_bfloat16 s0, s1;
    split2(h0[b * HID + u], s0, s1);
    g_h2[0][0][b * HID + u] = s0;
    g_h2[0][1][b * HID + u] = s1;
    g_c[b * HID + u] = 0.0f;
    if (u == 0) { g_tokpack[0][b] = 0ull; g_tokpack[1][b] = 0ull; }
}

// which: 0=Whh(perm,HID), 1=Wout(pad,HID), 2=emb(pad,WDIM), 3=Wih_word(perm,WDIM)
__global__ void split_kernel(const float* __restrict__ src, int which) {
    int r = blockIdx.x;
    int cols = (which >= 2) ? WDIM : HID;
    int srcld = (which == 3) ? LSTM_IN : cols;
    for (int k = threadIdx.x; k < cols; k += 256) {
        float x;
        if (which == 0)      x = src[(size_t)permrow(r) * srcld + k];
        else if (which == 1) x = (r < VOCAB) ? src[(size_t)r * srcld + k] : 0.0f;
        else if (which == 2) x = (r < VOCAB) ? src[(size_t)r * srcld + k] : 0.0f;
        else                 x = src[(size_t)permrow(r) * srcld + k];
        __nv_bfloat16 s0, s1;
        split2(x, s0, s1);
        size_t o = (size_t)r * cols + k;
        if (which == 0)      { g_Whh2[0][o] = s0;  g_Whh2[1][o] = s1; }
        else if (which == 1) { g_Wout2[0][o] = s0; g_Wout2[1][o] = s1; }
        else if (which == 2) { g_emb2[0][o] = s0;  g_emb2[1][o] = s1; }
        else                 { g_Wihw2[0][o] = s0; g_Wihw2[1][o] = s1; }
    }
}

// ---------------- a-chain mat-vecs ----------------
__global__ void matvecT_kernel(const float* __restrict__ Mt, int ld,
                               const float* __restrict__ vin_ext, int stage) {
    __shared__ float red[256];
    int j = blockIdx.x;
    const float* vin = (stage == 0) ? vin_ext : (stage == 1 ? g_a2 : g_a1);
    float acc = 0.0f;
    for (int h = threadIdx.x; h < HID; h += 256)
        acc += Mt[(size_t)h * ld + j] * vin[h];
    red[threadIdx.x] = acc;
    __syncthreads();
    for (int s = 128; s > 0; s >>= 1) {
        if (threadIdx.x < s) red[threadIdx.x] += red[threadIdx.x + s];
        __syncthreads();
    }
    if (threadIdx.x == 0) {
        float r = red[0];
        if (stage == 0)      g_a2[j]  = r;
        else if (stage == 1) g_a1[j]  = r;
        else                 g_a0e[j] = r;
    }
}

// ---------------- attention context (step-invariant) ----------------
__global__ void attn_ctx_kernel(const float* __restrict__ enc) {
    __shared__ float sa[HID];
    __shared__ float sE[SLEN];
    __shared__ float sW[SLEN];
    int b = blockIdx.x, tid = threadIdx.x;
    sa[tid] = g_a0e[tid];
    sa[tid + 256] = g_a0e[tid + 256];
    __syncthreads();
    int w = tid >> 5, lane = tid & 31;
    for (int s = w; s < SLEN; s += 8) {
        const float* row = enc + ((size_t)b * SLEN + s) * HID;
        float acc = 0.0f;
        for (int k = lane; k < HID; k += 32) acc += row[k] * sa[k];
        #pragma unroll
        for (int off = 16; off > 0; off >>= 1)
            acc += __shfl_xor_sync(0xffffffffu, acc, off);
        if (lane == 0) sE[s] = acc;
    }
    __syncthreads();
    if (tid < 32) {
        float v0 = (tid < SLEN) ? sE[tid] : -INFINITY;
        float v1 = (tid + 32 < SLEN) ? sE[tid + 32] : -INFINITY;
        float v2 = (tid + 64 < SLEN) ? sE[tid + 64] : -INFINITY;
        float m = fmaxf(v0, fmaxf(v1, v2));
        #pragma unroll
        for (int off = 16; off > 0; off >>= 1)
            m = fmaxf(m, __shfl_xor_sync(0xffffffffu, m, off));
        float e0 = (tid < SLEN) ? expf(v0 - m) : 0.0f;
        float e1 = (tid + 32 < SLEN) ? expf(v1 - m) : 0.0f;
        float e2 = (tid + 64 < SLEN) ? expf(v2 - m) : 0.0f;
        float s = e0 + e1 + e2;
        #pragma unroll
        for (int off = 16; off > 0; off >>= 1)
            s += __shfl_xor_sync(0xffffffffu, s, off);
        if (tid < SLEN)      sW[tid]      = e0 / s;
        if (tid + 32 < SLEN) sW[tid + 32] = e1 / s;
        if (tid + 64 < SLEN) sW[tid + 64] = e2 / s;
    }
    __syncthreads();
    for (int h = tid; h < HID; h += 256) {
        float acc = 0.0f;
        for (int s = 0; s < SLEN; s++)
            acc += sW[s] * enc[((size_t)b * SLEN + s) * HID + h];
        g_ctx[b * HID + h] = acc;
    }
}

// ---------------- FFMA2 Gbase GEMM (R4-proven; small, one-shot) -------------
__global__ __launch_bounds__(128, 4)
void pre_gemm_gbase(const float* __restrict__ Bp,
                    const float* __restrict__ bias1, const float* __restrict__ bias2) {
    __shared__ __align__(16) float As[2][64 * 32];
    __shared__ __align__(16) float Bs[2][64 * 32];

    const int tid = threadIdx.x;
    const int bm = blockIdx.y * 64;
    const int bn = blockIdx.x * 64;
    const int tm = tid >> 3;
    const int tn = tid & 7;

    const uint32_t sA = (uint32_t)__cvta_generic_to_shared(&As[0][0]);
    const uint32_t sB = (uint32_t)__cvta_generic_to_shared(&Bs[0][0]);

    const int ldrow = tid >> 1;
    const int ldcb  = (tid & 1) * 4;
    const int aswz  = (ldrow >> 2) & 7;
    const int bswz  = (ldrow >> 3) & 7;

    const float* a_srcbase = g_ctx + (size_t)(bm + ldrow) * HID + ldcb * 4;
    const float* b_srcbase = Bp + (size_t)permrow(bn + ldrow) * LSTM_IN + ldcb * 4;

    const uint32_t a_dst = sA + ldrow * 128;
    const uint32_t b_dst = sB + ldrow * 128;

    ull acc[4][8];
    #pragma unroll
    for (int i = 0; i < 4; i++)
        #pragma unroll
        for (int j = 0; j < 8; j++) acc[i][j] = 0ull;

    const int nch = HID >> 5;
    {
        #pragma unroll
        for (int jj = 0; jj < 4; jj++) {
            int c = ldcb + jj;
            CP_ASYNC16(a_dst + ((c ^ aswz) << 4), a_srcbase + jj * 4);
            CP_ASYNC16(b_dst + ((c ^ bswz) << 4), b_srcbase + jj * 4);
        }
        CP_COMMIT();
    }
    for (int ch = 0; ch < nch; ch++) {
        if (ch + 1 < nch) {
            int k0 = (ch + 1) << 5;
            uint32_t soff = ((ch + 1) & 1) ? 8192u : 0u;
            #pragma unroll
            for (int jj = 0; jj < 4; jj++) {
                int c = ldcb + jj;
                CP_ASYNC16(a_dst + soff + ((c ^ aswz) << 4), a_srcbase + k0 + jj * 4);
                CP_ASYNC16(b_dst + soff + ((c ^ bswz) << 4), b_srcbase + k0 + jj * 4);
            }
            CP_COMMIT();
            CP_WAIT1();
        } else {
            CP_WAIT0();
        }
        __syncthreads();

        const float* as = As[ch & 1];
        const float* bs = Bs[ch & 1];
        #pragma unroll
        for (int c = 0; c < 8; c++) {
            const int aoff = (c ^ (tm & 7)) << 2;
            const int boff = (c ^ tn) << 2;
            ulonglong2 av0 = *(const ulonglong2*)&as[(tm * 4 + 0) * 32 + aoff];
            ulonglong2 av1 = *(const ulonglong2*)&as[(tm * 4 + 1) * 32 + aoff];
            ulonglong2 av2 = *(const ulonglong2*)&as[(tm * 4 + 2) * 32 + aoff];
            ulonglong2 av3 = *(const ulonglong2*)&as[(tm * 4 + 3) * 32 + aoff];
            #pragma unroll
            for (int j = 0; j < 8; j++) {
                ulonglong2 bv = *(const ulonglong2*)&bs[(tn * 8 + j) * 32 + boff];
                acc[0][j] = ffma2(av0.x, bv.x, acc[0][j]);
                acc[0][j] = ffma2(av0.y, bv.y, acc[0][j]);
                acc[1][j] = ffma2(av1.x, bv.x, acc[1][j]);
                acc[1][j] = ffma2(av1.y, bv.y, acc[1][j]);
                acc[2][j] = ffma2(av2.x, bv.x, acc[2][j]);
                acc[2][j] = ffma2(av2.y, bv.y, acc[2][j]);
                acc[3][j] = ffma2(av3.x, bv.x, acc[3][j]);
                acc[3][j] = ffma2(av3.y, bv.y, acc[3][j]);
            }
        }
        __syncthreads();
    }

    const int ncol = bn + tn * 8;
    float badd[8];
    #pragma unroll
    for (int j = 0; j < 8; j++) {
        int pr = permrow(ncol + j);
        badd[j] = bias1[pr] + bias2[pr];
    }
    #pragma unroll
    for (int i = 0; i < 4; i++) {
        int m = bm + tm * 4 + i;
        float2 p0, p1, p2, p3;
        p0 = unpack2(acc[i][0]); p1 = unpack2(acc[i][1]);
        p2 = unpack2(acc[i][2]); p3 = unpack2(acc[i][3]);
        float4 v0 = make_float4(p0.x + p0.y + badd[0], p1.x + p1.y + badd[1],
                                p2.x + p2.y + badd[2], p3.x + p3.y + badd[3]);
        p0 = unpack2(acc[i][4]); p1 = unpack2(acc[i][5]);
        p2 = unpack2(acc[i][6]); p3 = unpack2(acc[i][7]);
        float4 v1 = make_float4(p0.x + p0.y + badd[4], p1.x + p1.y + badd[5],
                                p2.x + p2.y + badd[6], p3.x + p3.y + badd[7]);
        *reinterpret_cast<float4*>(g_Gbase + (size_t)m * NGATE + ncol)     = v0;
        *reinterpret_cast<float4*>(g_Gbase + (size_t)m * NGATE + ncol + 4) = v1;
    }
}

// ---------------- mma.sync 2-split / 3-product GEMM, 128xBN tile ------------
// BN = 64 (decode: MODE 1/2) or 128 (MODE 3 one-shot).
// products via PA/PB arrays: (0,0), (0,1), (1,0); (1,1) omitted (~2^-32 rel).
// MODE 1: gates = h[t] @ Whh^T + Gbase + Eproj[tok]; fused LSTM -> h[t+1], c
// MODE 2: logits = h[t+1] @ Wout^T + out_b; seq store + argmax (63 N-tiles)
// MODE 3: Eproj = emb @ Wih_word^T (one-shot precompute)
template <int MODE>
__global__ __launch_bounds__(256)
void mma_gemm(int t, const float* __restrict__ bias1,
              float* __restrict__ seq, float* __restrict__ pred) {
    constexpr int BN   = (MODE == 3) ? 128 : 64;
    constexpr int WN   = BN / 2;          // warp N tile
    constexpr int NT   = BN / 16;         // 8-col fragments per warp
    constexpr int NG   = BN / 32;         // 16-row B ldmatrix groups per warp
    constexpr uint32_t ASZ = 10240u;
    constexpr uint32_t BSZ = (uint32_t)BN * 80u;
    constexpr uint32_t STG = 2u * ASZ + 2u * BSZ;
    constexpr uint32_t SBB = 2u * STG;
    constexpr uint32_t SBT = SBB + 512u;
    constexpr int ACH = 1024;             // A 16B chunks per BK=32 chunk
    constexpr int BCH = BN * 8;           // B 16B chunks per BK=32 chunk
    constexpr int PER = (ACH + BCH) / 256;
    constexpr int EPS = BN + 4;           // epilogue smem row stride (floats)

    extern __shared__ __align__(16) char smem[];
    const uint32_t sbase = (uint32_t)__cvta_generic_to_shared(smem);

    const int tid = threadIdx.x;
    const int wid = tid >> 5;
    const int lane = tid & 31;
    const int bm = blockIdx.y * 128;
    const int bn = blockIdx.x * BN;
    const int wm = (wid & 3) * 32;
    const int wn = (wid >> 2) * WN;

    const int K = (MODE == 3) ? WDIM : HID;
    const __nv_bfloat16* Aps[2];
    const __nv_bfloat16* Bps[2];
    if (MODE == 1) {
        Aps[0] = g_h2[t & 1][0];  Aps[1] = g_h2[t & 1][1];
        Bps[0] = g_Whh2[0];       Bps[1] = g_Whh2[1];
    } else if (MODE == 2) {
        Aps[0] = g_h2[(t + 1) & 1][0]; Aps[1] = g_h2[(t + 1) & 1][1];
        Bps[0] = g_Wout2[0];           Bps[1] = g_Wout2[1];
    } else {
        Aps[0] = g_emb2[0];  Aps[1] = g_emb2[1];
        Bps[0] = g_Wihw2[0]; Bps[1] = g_Wihw2[1];
    }

    int* stok = (int*)(smem + SBT);
    float* sbias = (float*)(smem + SBB);
    if (MODE == 1 && tid < 128)
        stok[tid] = (t == 0) ? 1 : decode_tok(g_tokpack[(t - 1) & 1][bm + tid]);
    if (MODE == 2) {
        if (blockIdx.x == 0 && tid < 128) g_tokpack[(t + 1) & 1][bm + tid] = 0ull;
        if (tid < BN) {
            int n = bn + tid;
            sbias[tid] = (n < VOCAB) ? bias1[n] : -3e38f;
        }
    }

    float acc[2][NT][4];
    #pragma unroll
    for (int i = 0; i < 2; i++)
        #pragma unroll
        for (int j = 0; j < NT; j++)
            #pragma unroll
            for (int k = 0; k < 4; k++) acc[i][j][k] = 0.0f;

    auto load_chunk = [&](int ch, int st) {
        const int k0 = ch << 5;
        #pragma unroll
        for (int i = 0; i < PER; i++) {
            int idx = i * 256 + tid;
            uint32_t dst;
            const __nv_bfloat16* src;
            if (idx < ACH) {
                int s = idx >> 9, rem = idx & 511, r = rem >> 2, c = rem & 3;
                dst = sbase + st * STG + s * ASZ + r * 80 + c * 16;
                src = Aps[s] + (size_t)(bm + r) * K + k0 + c * 8;
            } else {
                int j = idx - ACH;
                int s = j / (BN * 4), rem = j % (BN * 4), r = rem >> 2, c = rem & 3;
                dst = sbase + st * STG + 2 * ASZ + s * BSZ + r * 80 + c * 16;
                src = Bps[s] + (size_t)(bn + r) * K + k0 + c * 8;
            }
            CP_ASYNC16(dst, src);
        }
        CP_COMMIT();
    };

    const int nch = K >> 5;
    load_chunk(0, 0);
    for (int ch = 0; ch < nch; ch++) {
        if (ch + 1 < nch) { load_chunk(ch + 1, (ch + 1) & 1); CP_WAIT1(); }
        else              { CP_WAIT0(); }
        __syncthreads();

        const int st = ch & 1;
        #pragma unroll
        for (int ks = 0; ks < 2; ks++) {
            uint32_t af[2][2][4], bf[2][NG][4];
            #pragma unroll
            for (int s = 0; s < 2; s++) {
                #pragma unroll
                for (int mt = 0; mt < 2; mt++)
                    ldm_x4(af[s][mt], sbase + st * STG + s * ASZ +
                           (wm + mt * 16 + (lane & 15)) * 80 + ks * 32 +
                           ((lane >> 4) << 4));
                #pragma unroll
                for (int g = 0; g < NG; g++)
                    ldm_x4(bf[s][g], sbase + st * STG + 2 * ASZ + s * BSZ +
                           (wn + g * 16 + (lane & 15)) * 80 + ks * 32 +
                           ((lane >> 4) << 4));
            }
            const int PA[3] = {0, 0, 1};
            const int PB[3] = {0, 1, 0};
            #pragma unroll
            for (int p = 0; p < 3; p++) {
                #pragma unroll
                for (int mt = 0; mt < 2; mt++)
                    #pragma unroll
                    for (int nt = 0; nt < NT; nt++) {
                        int g = nt >> 1, h = nt & 1;
                        mma16816(acc[mt][nt], af[PA[p]][mt],
                                 bf[PB[p]][g][h], bf[PB[p]][g][h + 2]);
                    }
            }
        }
        __syncthreads();
    }

    // accumulators -> smem tile [128][EPS] f32 (reuses stage buffers)
    float* ep = (float*)smem;
    #pragma unroll
    for (int mt = 0; mt < 2; mt++)
        #pragma unroll
        for (int nt = 0; nt < NT; nt++) {
            int row = wm + mt * 16 + (lane >> 2);
            int col = wn + nt * 8 + (lane & 3) * 2;
            float b0 = 0.0f, b1 = 0.0f;
            if (MODE == 2) { b0 = sbias[col]; b1 = sbias[col + 1]; }
            ep[row * EPS + col]           = acc[mt][nt][0] + b0;
            ep[row * EPS + col + 1]       = acc[mt][nt][1] + b1;
            ep[(row + 8) * EPS + col]     = acc[mt][nt][2] + b0;
            ep[(row + 8) * EPS + col + 1] = acc[mt][nt][3] + b1;
        }
    __syncthreads();

    const int m = tid >> 1;
    const int mg = bm + m;
    if (MODE == 1) {
        const int tok = stok[m];
        const int uo = (tid & 1) * 8;
        const int ho = (t + 1) & 1;
        #pragma unroll
        for (int j = 0; j < 8; j++) {
            int col = (uo + j) * 4;
            int gcol = bn + col;
            int u = gcol >> 2;
            float4 gb = *(const float4*)&g_Gbase[(size_t)mg * NGATE + gcol];
            float4 epj = *(const float4*)&g_Eproj[(size_t)tok * NGATE + gcol];
            float gi = ep[m * EPS + col]     + gb.x + epj.x;
            float gf = ep[m * EPS + col + 1] + gb.y + epj.y;
            float gg = ep[m * EPS + col + 2] + gb.z + epj.z;
            float go = ep[m * EPS + col + 3] + gb.w + epj.w;
            float cn = sigmoidf_(gf) * g_c[mg * HID + u] + sigmoidf_(gi) * tanhf(gg);
            g_c[mg * HID + u] = cn;
            float hn = sigmoidf_(go) * tanhf(cn);
            __nv_bfloat16 s0, s1;
            split2(hn, s0, s1);
            g_h2[ho][0][mg * HID + u] = s0;
            g_h2[ho][1][mg * HID + u] = s1;
        }
        if (blockIdx.x == 0 && (tid & 1) == 0 && t > 0 && pred)
            pred[mg * TSTEPS + (t - 1)] = (float)tok;
    } else if (MODE == 2) {
        const int cs = (tid & 1) * WN;
        ull best = 0ull;
        #pragma unroll
        for (int k = 0; k < WN; k++) {
            float v = ep[m * EPS + cs + k];
            unsigned n = (unsigned)(bn + cs + k);
            ull cand = ((ull)f2ord(v) << 32) | (ull)(0xFFFFFFFFu - n);
            if (cand > best) best = cand;
        }
        ull o = __shfl_xor_sync(0xffffffffu, best, 1);
        if (o > best) best = o;
        if ((tid & 1) == 0) atomicMax(&g_tokpack[t & 1][mg], best);
        if (seq) {
            float* orow = seq + (size_t)mg * (TSTEPS * VOCAB) + (size_t)t * VOCAB;
            #pragma unroll
            for (int k4 = 0; k4 < WN / 4; k4++) {
                int n = bn + cs + k4 * 4;
                if (n + 3 < VOCAB) {
                    *(float4*)&orow[n] = make_float4(
                        ep[m * EPS + cs + k4 * 4],     ep[m * EPS + cs + k4 * 4 + 1],
                        ep[m * EPS + cs + k4 * 4 + 2], ep[m * EPS + cs + k4 * 4 + 3]);
                } else {
                    for (int q = 0; q < 4; q++)
                        if (n + q < VOCAB) orow[n + q] = ep[m * EPS + cs + k4 * 4 + q];
                }
            }
        }
    } else {  // MODE 3: Eproj store
        if (mg < VOCAB) {
            const int cs = (tid & 1) * WN;
            float* orow = g_Eproj + (size_t)mg * NGATE + bn;
            #pragma unroll
            for (int k4 = 0; k4 < WN / 4; k4++)
                *(float4*)&orow[cs + k4 * 4] = make_float4(
                    ep[m * EPS + cs + k4 * 4],     ep[m * EPS + cs + k4 * 4 + 1],
                    ep[m * EPS + cs + k4 * 4 + 2], ep[m * EPS + cs + k4 * 4 + 3]);
        }
    }
}

// ---------------- final pred ----------------
__global__ void final_pred_kernel(float* __restrict__ pred) {
    int b = threadIdx.x;
    pred[b * TSTEPS + (TSTEPS - 1)] = (float)decode_tok(g_tokpack[(TSTEPS - 1) & 1][b]);
}

// ---------------- launch ----------------
extern "C" void kernel_launch(void* const* d_in, const int* in_sizes, int n_in,
                              void* d_out, int out_size) {
    const float* enc_last = (const float*)d_in[0];
    const float* enc_out  = (const float*)d_in[1];
    const float* emb      = (const float*)d_in[2];
    const float* w1       = (const float*)d_in[3];
    const float* w2       = (const float*)d_in[5];
    const float* w3       = (const float*)d_in[7];
    const float* wv       = (const float*)d_in[9];
    const float* w_ih     = (const float*)d_in[10];
    const float* w_hh     = (const float*)d_in[11];
    const float* b_ih     = (const float*)d_in[12];
    const float* b_hh     = (const float*)d_in[13];
    const float* out_w    = (const float*)d_in[14];
    const float* out_b    = (const float*)d_in[15];

    float* out = (float*)d_out;
    const long long SEQ = (long long)BATCH * TSTEPS * VOCAB;
    const long long PRED = (long long)BATCH * TSTEPS;
    float* seq_ptr = ((long long)out_size >= SEQ) ? out : nullptr;
    float* pred_ptr = ((long long)out_size >= SEQ + PRED) ? (out + SEQ) : nullptr;

    cudaFuncSetAttribute(mma_gemm<1>, cudaFuncAttributeMaxDynamicSharedMemorySize, MM_SMEM_64);
    cudaFuncSetAttribute(mma_gemm<2>, cudaFuncAttributeMaxDynamicSharedMemorySize, MM_SMEM_64);
    cudaFuncSetAttribute(mma_gemm<3>, cudaFuncAttributeMaxDynamicSharedMemorySize, MM_SMEM_128);

    // precompute
    init_hc_kernel<<<BATCH, HID>>>(enc_last);
    matvecT_kernel<<<HID, 256>>>(w3, HID, wv, 0);
    matvecT_kernel<<<HID, 256>>>(w2, HID, nullptr, 1);
    matvecT_kernel<<<HID, 256>>>(w1, WDIM, nullptr, 2);
    attn_ctx_kernel<<<BATCH, 256>>>(enc_out);

    split_kernel<<<NGATE, 256>>>(w_hh, 0);   // Whh2 (perm)
    split_kernel<<<VPAD, 256>>>(out_w, 1);   // Wout2 (pad)
    split_kernel<<<VPAD, 256>>>(emb, 2);     // emb2 (pad)
    split_kernel<<<NGATE, 256>>>(w_ih, 3);   // Wihw2 (perm, word cols)

    pre_gemm_gbase<<<dim3(NGATE / 64, BATCH / 64), 128>>>(w_ih + WDIM, b_ih, b_hh);

    // Eproj on tensor cores (one-shot, BN=128)
    mma_gemm<3><<<dim3(NGATE / 128, VPAD / 128), 256, MM_SMEM_128>>>(
        0, nullptr, nullptr, nullptr);

    // 27 decode steps on mma.sync tensor cores
    for (int t = 0; t < TSTEPS; t++) {
        mma_gemm<1><<<dim3(NGATE / 64, BATCH / 128), 256, MM_SMEM_64>>>(
            t, nullptr, nullptr, pred_ptr);
        // logits: 63 N-tiles cover 4032 >= VOCAB (cols 4004..4031 hit sentinel bias)
        mma_gemm<2><<<dim3(63, BATCH / 128), 256, MM_SMEM_64>>>(
            t, out_b, seq_ptr, nullptr);
    }
    if (pred_ptr)
        final_pred_kernel<<<1, BATCH>>>(pred_ptr);
}